// round 14
// baseline (speedup 1.0000x reference)
#include <cuda_runtime.h>
#include <cuda_fp16.h>
#include <mma.h>
#include <cstdint>

using namespace nvcuda;

#define N_NODES 100000
#define N_EDGES 1600000
#define IN_F 64
#define OUT_F 64
#define SUPPORT 3
#define CAT_F (SUPPORT * IN_F)                     // 192

#define M_BINS (SUPPORT * N_NODES)                 // 300000 (k,row) bins
#define TOT_E  (SUPPORT * N_EDGES)                 // 4.8M edges
#define SCAN_BS 1024
#define NBLK ((M_BINS + SCAN_BS - 1) / SCAN_BS)    // 293

// ---- static scratch (no runtime allocation) -------------------------------
__device__ __half             g_Xh[(size_t)N_NODES * IN_F];            // 12.8 MB fp16 X (gather target)
__device__ __half             g_Yh[(size_t)(M_BINS + 64) * IN_F];      // fp16 Y (+pad rows for wmma tail)
__device__ __half             g_Wh[CAT_F * OUT_F];                     // 24 KB fp16 W
__device__ int                g_count[M_BINS];
__device__ int                g_start[M_BINS + 1];
__device__ int                g_cursor[M_BINS];
__device__ int                g_partial[SCAN_BS];
__device__ unsigned long long g_pairs[TOT_E];      // (val<<32 | col), bin-sorted

// ---------------------------------------------------------------------------
// prep: X->Xh, W->Wh, zero histogram bins (one launch).
// ---------------------------------------------------------------------------
__global__ __launch_bounds__(256) void prep_kernel(const float* __restrict__ X,
                                                   const float* __restrict__ W) {
    int i = blockIdx.x * 256 + threadIdx.x;            // float4 index
    if (i < N_NODES * IN_F / 4) {
        float4 v = reinterpret_cast<const float4*>(X)[i];
        __half2 h0 = __floats2half2_rn(v.x, v.y);
        __half2 h1 = __floats2half2_rn(v.z, v.w);
        uint2 pk = make_uint2(*reinterpret_cast<unsigned int*>(&h0),
                              *reinterpret_cast<unsigned int*>(&h1));
        reinterpret_cast<uint2*>(g_Xh)[i] = pk;
    }
    if (i < CAT_F * OUT_F / 4) {
        float4 v = reinterpret_cast<const float4*>(W)[i];
        __half2 h0 = __floats2half2_rn(v.x, v.y);
        __half2 h1 = __floats2half2_rn(v.z, v.w);
        uint2 pk = make_uint2(*reinterpret_cast<unsigned int*>(&h0),
                              *reinterpret_cast<unsigned int*>(&h1));
        reinterpret_cast<uint2*>(g_Wh)[i] = pk;
    }
    if (i < M_BINS) g_count[i] = 0;
}

// ---------------------------------------------------------------------------
// Counting sort by (support, destination row)
// ---------------------------------------------------------------------------
__global__ __launch_bounds__(256) void hist_kernel(const int* __restrict__ rows) {
    int g = blockIdx.x * 256 + threadIdx.x;
    if (g >= TOT_E / 4) return;
    int  e0 = g * 4;
    int  k  = e0 / N_EDGES;
    int4 r4 = *reinterpret_cast<const int4*>(rows + e0);
    int  kb = k * N_NODES;
    atomicAdd(&g_count[kb + r4.x], 1);
    atomicAdd(&g_count[kb + r4.y], 1);
    atomicAdd(&g_count[kb + r4.z], 1);
    atomicAdd(&g_count[kb + r4.w], 1);
}

__global__ __launch_bounds__(SCAN_BS) void scanA_kernel() {
    __shared__ int s[SCAN_BS];
    int t = threadIdx.x;
    int i = blockIdx.x * SCAN_BS + t;
    int v = (i < M_BINS) ? g_count[i] : 0;
    s[t] = v;
    __syncthreads();
    #pragma unroll
    for (int off = 1; off < SCAN_BS; off <<= 1) {
        int x = (t >= off) ? s[t - off] : 0;
        __syncthreads();
        s[t] += x;
        __syncthreads();
    }
    if (i < M_BINS) g_start[i] = s[t] - v;
    if (t == SCAN_BS - 1) g_partial[blockIdx.x] = s[t];
}

// scanC: each block reduces partials[0..bid) itself.
__global__ __launch_bounds__(SCAN_BS) void scanC_kernel() {
    __shared__ int s[SCAN_BS];
    int t = threadIdx.x;
    int v = (t < (int)blockIdx.x && t < NBLK) ? g_partial[t] : 0;
    s[t] = v;
    __syncthreads();
    #pragma unroll
    for (int off = SCAN_BS / 2; off > 0; off >>= 1) {
        if (t < off) s[t] += s[t + off];
        __syncthreads();
    }
    int prefix = s[0];

    int i = blockIdx.x * SCAN_BS + t;
    if (i < M_BINS) {
        int st = g_start[i] + prefix;
        g_start[i]  = st;
        g_cursor[i] = st;
    }
    if (blockIdx.x == 0 && t == 0) g_start[M_BINS] = TOT_E;
}

__global__ __launch_bounds__(256) void scatter_kernel(const int* __restrict__ rows,
                                                      const int* __restrict__ cols,
                                                      const float* __restrict__ vals) {
    int g = blockIdx.x * 256 + threadIdx.x;
    if (g >= TOT_E / 4) return;
    int    e0 = g * 4;
    int    k  = e0 / N_EDGES;
    int4   r4 = *reinterpret_cast<const int4*>(rows + e0);
    int4   c4 = *reinterpret_cast<const int4*>(cols + e0);
    float4 v4 = *reinterpret_cast<const float4*>(vals + e0);
    int    kb = k * N_NODES;

    int p0 = atomicAdd(&g_cursor[kb + r4.x], 1);
    int p1 = atomicAdd(&g_cursor[kb + r4.y], 1);
    int p2 = atomicAdd(&g_cursor[kb + r4.z], 1);
    int p3 = atomicAdd(&g_cursor[kb + r4.w], 1);

    g_pairs[p0] = ((unsigned long long)__float_as_uint(v4.x) << 32) | (unsigned int)c4.x;
    g_pairs[p1] = ((unsigned long long)__float_as_uint(v4.y) << 32) | (unsigned int)c4.y;
    g_pairs[p2] = ((unsigned long long)__float_as_uint(v4.z) << 32) | (unsigned int)c4.z;
    g_pairs[p3] = ((unsigned long long)__float_as_uint(v4.w) << 32) | (unsigned int)c4.w;
}

// ---------------------------------------------------------------------------
// SpMM accumulate: one warp per node. Quarter-warp edge split (R13):
// lane groups 0-3 (8 lanes each) handle edges e+0..e+3 of each 4-edge step;
// each lane loads 16B (LDG.128) -> one gather covers FOUR edges (512B).
// NEW (R14): the tail is a single BRANCHLESS predicated 4-slot block —
// up to 16 remaining edges processed in ONE latency window instead of up
// to 4 serial ones. p=0 => val 0.0 (harmless row-0 gather).
// fp32 accumulation, fp16 Y output (one STG.128 per 8 lanes).
// ---------------------------------------------------------------------------
__device__ __forceinline__ void gather8(unsigned long long p, int fl,
                                        float4& a0, float4& a1) {
    uint4 g = __ldg(reinterpret_cast<const uint4*>(
        g_Xh + (size_t)(unsigned int)p * IN_F + fl * 8));
    float2 f0 = __half22float2(*reinterpret_cast<__half2*>(&g.x));
    float2 f1 = __half22float2(*reinterpret_cast<__half2*>(&g.y));
    float2 f2 = __half22float2(*reinterpret_cast<__half2*>(&g.z));
    float2 f3 = __half22float2(*reinterpret_cast<__half2*>(&g.w));
    float  v  = __uint_as_float((unsigned int)(p >> 32));
    a0.x += v * f0.x; a0.y += v * f0.y;
    a0.z += v * f1.x; a0.w += v * f1.y;
    a1.x += v * f2.x; a1.y += v * f2.y;
    a1.z += v * f3.x; a1.w += v * f3.y;
}

__global__ __launch_bounds__(256) void accum_kernel() {
    int t    = blockIdx.x * 256 + threadIdx.x;
    int n    = t >> 5;
    int lane = t & 31;
    if (n >= N_NODES) return;

    const int grp = lane >> 3;         // 0..3: which edge of each 4-edge step
    const int fl  = lane & 7;          // feature octet owned: [fl*8, fl*8+8)

    #pragma unroll
    for (int k = 0; k < SUPPORT; k++) {
        int bin  = k * N_NODES + n;
        int e    = __ldg(&g_start[bin]);
        int eend = __ldg(&g_start[bin + 1]);

        float4 a0 = make_float4(0.f, 0.f, 0.f, 0.f);
        float4 a1 = make_float4(0.f, 0.f, 0.f, 0.f);

        // Full 16-edge blocks: 4 four-edge gathers in flight.
        for (; e + 16 <= eend; e += 16) {
            unsigned long long q0 = __ldg(g_pairs + e + 0  + grp);
            unsigned long long q1 = __ldg(g_pairs + e + 4  + grp);
            unsigned long long q2 = __ldg(g_pairs + e + 8  + grp);
            unsigned long long q3 = __ldg(g_pairs + e + 12 + grp);
            gather8(q0, fl, a0, a1);
            gather8(q1, fl, a0, a1);
            gather8(q2, fl, a0, a1);
            gather8(q3, fl, a0, a1);
        }

        // Branchless wide tail: up to 15 remaining edges, 4 predicated
        // independent slots -> ONE latency window.
        if (e < eend) {
            int i0 = e + 0  + grp;
            int i1 = e + 4  + grp;
            int i2 = e + 8  + grp;
            int i3 = e + 12 + grp;
            unsigned long long q0 = (i0 < eend) ? __ldg(g_pairs + i0) : 0ULL;
            unsigned long long q1 = (i1 < eend) ? __ldg(g_pairs + i1) : 0ULL;
            unsigned long long q2 = (i2 < eend) ? __ldg(g_pairs + i2) : 0ULL;
            unsigned long long q3 = (i3 < eend) ? __ldg(g_pairs + i3) : 0ULL;
            gather8(q0, fl, a0, a1);
            gather8(q1, fl, a0, a1);
            gather8(q2, fl, a0, a1);
            gather8(q3, fl, a0, a1);
        }

        // Reduce across the 4 lane groups (xor 8, then xor 16).
        #pragma unroll
        for (int off = 8; off <= 16; off <<= 1) {
            a0.x += __shfl_xor_sync(0xffffffffu, a0.x, off);
            a0.y += __shfl_xor_sync(0xffffffffu, a0.y, off);
            a0.z += __shfl_xor_sync(0xffffffffu, a0.z, off);
            a0.w += __shfl_xor_sync(0xffffffffu, a0.w, off);
            a1.x += __shfl_xor_sync(0xffffffffu, a1.x, off);
            a1.y += __shfl_xor_sync(0xffffffffu, a1.y, off);
            a1.z += __shfl_xor_sync(0xffffffffu, a1.z, off);
            a1.w += __shfl_xor_sync(0xffffffffu, a1.w, off);
        }

        if (grp == 0) {
            __half2 h0 = __floats2half2_rn(a0.x, a0.y);
            __half2 h1 = __floats2half2_rn(a0.z, a0.w);
            __half2 h2 = __floats2half2_rn(a1.x, a1.y);
            __half2 h3 = __floats2half2_rn(a1.z, a1.w);
            uint4 pk = make_uint4(*reinterpret_cast<unsigned int*>(&h0),
                                  *reinterpret_cast<unsigned int*>(&h1),
                                  *reinterpret_cast<unsigned int*>(&h2),
                                  *reinterpret_cast<unsigned int*>(&h3));
            *reinterpret_cast<uint4*>(
                g_Yh + ((size_t)k * N_NODES + n) * IN_F + fl * 8) = pk;
        }
    }
}

// ---------------------------------------------------------------------------
// Tensor-core GEMM: out[n][:] = bias + sum_k Yh[k][n][:] @ Wh[k*64:(k+1)*64][:]
// (R10 proven form.)
// ---------------------------------------------------------------------------
__global__ __launch_bounds__(256) void gemm_tc_kernel(const float* __restrict__ bias,
                                                      float* __restrict__ out) {
    __shared__ float Cs[64][72];               // 18.4 KB

    const int tid   = threadIdx.x;
    const int warp  = tid >> 5;
    const int rbase = blockIdx.x * 64;
    const int mt    = warp & 3;                // m-tile (16 rows)
    const int ntb   = (warp >> 2) * 2;         // first of two n-tiles

    wmma::fragment<wmma::accumulator, 16, 16, 16, float> c0, c1;
    wmma::fill_fragment(c0, 0.f);
    wmma::fill_fragment(c1, 0.f);

    #pragma unroll
    for (int ks = 0; ks < SUPPORT; ks++) {
        const __half* Yk  = g_Yh + (size_t)ks * N_NODES * IN_F;
        const __half* Apt = Yk + (size_t)(rbase + mt * 16) * IN_F;
        #pragma unroll
        for (int kc = 0; kc < 4; kc++) {       // 4 x 16 = 64 K per support
            wmma::fragment<wmma::matrix_a, 16, 16, 16, __half, wmma::row_major> a;
            wmma::load_matrix_sync(a, Apt + kc * 16, IN_F);

            const __half* Bpt = g_Wh + (size_t)(ks * 64 + kc * 16) * OUT_F;
            wmma::fragment<wmma::matrix_b, 16, 16, 16, __half, wmma::row_major> b0, b1;
            wmma::load_matrix_sync(b0, Bpt + ntb * 16, OUT_F);
            wmma::load_matrix_sync(b1, Bpt + (ntb + 1) * 16, OUT_F);

            wmma::mma_sync(c0, a, b0, c0);
            wmma::mma_sync(c1, a, b1, c1);
        }
    }

    wmma::store_matrix_sync(&Cs[mt * 16][ntb * 16],       c0, 72, wmma::mem_row_major);
    wmma::store_matrix_sync(&Cs[mt * 16][(ntb + 1) * 16], c1, 72, wmma::mem_row_major);
    __syncthreads();

    #pragma unroll
    for (int i = tid; i < 64 * 16; i += 256) {
        int r  = i >> 4;
        int c4 = i & 15;
        int gr = rbase + r;
        if (gr < N_NODES) {
            float4 b4 = *reinterpret_cast<const float4*>(bias + c4 * 4);
            float4 o  = make_float4(Cs[r][c4 * 4 + 0] + b4.x,
                                    Cs[r][c4 * 4 + 1] + b4.y,
                                    Cs[r][c4 * 4 + 2] + b4.z,
                                    Cs[r][c4 * 4 + 3] + b4.w);
            *reinterpret_cast<float4*>(out + (size_t)gr * OUT_F + c4 * 4) = o;
        }
    }
}

// ---------------------------------------------------------------------------
extern "C" void kernel_launch(void* const* d_in, const int* in_sizes, int n_in,
                              void* d_out, int out_size) {
    const float* X     = (const float*)d_in[0];
    const int*   erows = (const int*)  d_in[1];
    const int*   ecols = (const int*)  d_in[2];
    const float* evals = (const float*)d_in[3];
    const float* W     = (const float*)d_in[4];
    const float* bias  = (const float*)d_in[5];
    float*       out   = (float*)d_out;

    // prep: X->fp16, W->fp16, zero bins (one launch)
    prep_kernel<<<(N_NODES * IN_F / 4 + 255) / 256, 256>>>(X, W);

    // Counting sort of edges by (support, dest row)
    int ebl4 = (TOT_E / 4 + 255) / 256;
    hist_kernel<<<ebl4, 256>>>(erows);
    scanA_kernel<<<NBLK, SCAN_BS>>>();
    scanC_kernel<<<NBLK, SCAN_BS>>>();
    scatter_kernel<<<ebl4, 256>>>(erows, ecols, evals);

    // Y[k][n] = (S_k @ Xh)[n]; warp per node, quarter-warp split + wide tail
    int ablocks = (N_NODES * 32 + 255) / 256;
    accum_kernel<<<ablocks, 256>>>();

    // out = concat_k(Y_k) @ W + bias on tensor cores
    gemm_tc_kernel<<<(N_NODES + 63) / 64, 256>>>(bias, out);
}

// round 15
// speedup vs baseline: 1.0253x; 1.0253x over previous
#include <cuda_runtime.h>
#include <cuda_fp16.h>
#include <mma.h>
#include <cstdint>

using namespace nvcuda;

#define N_NODES 100000
#define N_EDGES 1600000
#define IN_F 64
#define OUT_F 64
#define SUPPORT 3
#define CAT_F (SUPPORT * IN_F)                     // 192

#define M_BINS (SUPPORT * N_NODES)                 // 300000 (k,row) bins
#define TOT_E  (SUPPORT * N_EDGES)                 // 4.8M edges
#define SCAN_BS 1024
#define NBLK ((M_BINS + SCAN_BS - 1) / SCAN_BS)    // 293

// ---- static scratch (no runtime allocation) -------------------------------
__device__ __half             g_Xh[(size_t)N_NODES * IN_F];            // 12.8 MB fp16 X (gather target)
__device__ __half             g_Yh[(size_t)(M_BINS + 64) * IN_F];      // fp16 Y (+pad rows for wmma tail)
__device__ __half             g_Wh[CAT_F * OUT_F];                     // 24 KB fp16 W
__device__ int                g_count[M_BINS];
__device__ int                g_start[M_BINS + 1];
__device__ int                g_partial[SCAN_BS];
__device__ unsigned short     g_rank[TOT_E];       // within-bin rank per edge (9.6 MB)
__device__ unsigned int       g_pairs[TOT_E];      // (val_fp16_15b << 17 | col), bin-sorted (19.2 MB)

// ---------------------------------------------------------------------------
// prep: X->Xh, W->Wh, zero histogram bins (one launch).
// ---------------------------------------------------------------------------
__global__ __launch_bounds__(256) void prep_kernel(const float* __restrict__ X,
                                                   const float* __restrict__ W) {
    int i = blockIdx.x * 256 + threadIdx.x;            // float4 index
    if (i < N_NODES * IN_F / 4) {
        float4 v = reinterpret_cast<const float4*>(X)[i];
        __half2 h0 = __floats2half2_rn(v.x, v.y);
        __half2 h1 = __floats2half2_rn(v.z, v.w);
        uint2 pk = make_uint2(*reinterpret_cast<unsigned int*>(&h0),
                              *reinterpret_cast<unsigned int*>(&h1));
        reinterpret_cast<uint2*>(g_Xh)[i] = pk;
    }
    if (i < CAT_F * OUT_F / 4) {
        float4 v = reinterpret_cast<const float4*>(W)[i];
        __half2 h0 = __floats2half2_rn(v.x, v.y);
        __half2 h1 = __floats2half2_rn(v.z, v.w);
        uint2 pk = make_uint2(*reinterpret_cast<unsigned int*>(&h0),
                              *reinterpret_cast<unsigned int*>(&h1));
        reinterpret_cast<uint2*>(g_Wh)[i] = pk;
    }
    if (i < M_BINS) g_count[i] = 0;
}

// ---------------------------------------------------------------------------
// Counting sort by (support, destination row). hist stores each edge's
// within-bin rank (the atomicAdd return) so scatter needs NO atomics.
// ---------------------------------------------------------------------------
__global__ __launch_bounds__(256) void hist_kernel(const int* __restrict__ rows) {
    int g = blockIdx.x * 256 + threadIdx.x;
    if (g >= TOT_E / 4) return;
    int  e0 = g * 4;
    int  k  = e0 / N_EDGES;
    int4 r4 = *reinterpret_cast<const int4*>(rows + e0);
    int  kb = k * N_NODES;
    int k0 = atomicAdd(&g_count[kb + r4.x], 1);
    int k1 = atomicAdd(&g_count[kb + r4.y], 1);
    int k2 = atomicAdd(&g_count[kb + r4.z], 1);
    int k3 = atomicAdd(&g_count[kb + r4.w], 1);
    ushort4 rk = make_ushort4((unsigned short)k0, (unsigned short)k1,
                              (unsigned short)k2, (unsigned short)k3);
    *reinterpret_cast<ushort4*>(g_rank + e0) = rk;
}

__global__ __launch_bounds__(SCAN_BS) void scanA_kernel() {
    __shared__ int s[SCAN_BS];
    int t = threadIdx.x;
    int i = blockIdx.x * SCAN_BS + t;
    int v = (i < M_BINS) ? g_count[i] : 0;
    s[t] = v;
    __syncthreads();
    #pragma unroll
    for (int off = 1; off < SCAN_BS; off <<= 1) {
        int x = (t >= off) ? s[t - off] : 0;
        __syncthreads();
        s[t] += x;
        __syncthreads();
    }
    if (i < M_BINS) g_start[i] = s[t] - v;
    if (t == SCAN_BS - 1) g_partial[blockIdx.x] = s[t];
}

// scanC: each block reduces partials[0..bid) itself.
__global__ __launch_bounds__(SCAN_BS) void scanC_kernel() {
    __shared__ int s[SCAN_BS];
    int t = threadIdx.x;
    int v = (t < (int)blockIdx.x && t < NBLK) ? g_partial[t] : 0;
    s[t] = v;
    __syncthreads();
    #pragma unroll
    for (int off = SCAN_BS / 2; off > 0; off >>= 1) {
        if (t < off) s[t] += s[t + off];
        __syncthreads();
    }
    int prefix = s[0];

    int i = blockIdx.x * SCAN_BS + t;
    if (i < M_BINS) g_start[i] += prefix;
    if (blockIdx.x == 0 && t == 0) g_start[M_BINS] = TOT_E;
}

// Atomic-free scatter: pos = g_start[bin] + rank[e]. 4B packed payload:
// (fp16 bits of val, sign always 0 -> 15 bits) << 17 | col (<2^17).
__global__ __launch_bounds__(256) void scatter_kernel(const int* __restrict__ rows,
                                                      const int* __restrict__ cols,
                                                      const float* __restrict__ vals) {
    int g = blockIdx.x * 256 + threadIdx.x;
    if (g >= TOT_E / 4) return;
    int    e0 = g * 4;
    int    k  = e0 / N_EDGES;
    int4   r4 = *reinterpret_cast<const int4*>(rows + e0);
    int4   c4 = *reinterpret_cast<const int4*>(cols + e0);
    float4 v4 = *reinterpret_cast<const float4*>(vals + e0);
    ushort4 rk = *reinterpret_cast<const ushort4*>(g_rank + e0);
    int    kb = k * N_NODES;

    int p0 = __ldg(&g_start[kb + r4.x]) + rk.x;
    int p1 = __ldg(&g_start[kb + r4.y]) + rk.y;
    int p2 = __ldg(&g_start[kb + r4.z]) + rk.z;
    int p3 = __ldg(&g_start[kb + r4.w]) + rk.w;

    unsigned int q0 = ((unsigned int)__half_as_ushort(__float2half_rn(v4.x)) << 17) | (unsigned int)c4.x;
    unsigned int q1 = ((unsigned int)__half_as_ushort(__float2half_rn(v4.y)) << 17) | (unsigned int)c4.y;
    unsigned int q2 = ((unsigned int)__half_as_ushort(__float2half_rn(v4.z)) << 17) | (unsigned int)c4.z;
    unsigned int q3 = ((unsigned int)__half_as_ushort(__float2half_rn(v4.w)) << 17) | (unsigned int)c4.w;

    g_pairs[p0] = q0;
    g_pairs[p1] = q1;
    g_pairs[p2] = q2;
    g_pairs[p3] = q3;
}

// ---------------------------------------------------------------------------
// SpMM accumulate: one warp per node, quarter-warp edge split (R13/R14 form,
// only the pair decode changed to the 4B packed format).
// p==0 => val bits 0 => 0.0f (harmless row-0 gather).
// ---------------------------------------------------------------------------
__device__ __forceinline__ void gather8(unsigned int p, int fl,
                                        float4& a0, float4& a1) {
    unsigned int col = p & 0x1FFFFu;
    uint4 g = __ldg(reinterpret_cast<const uint4*>(
        g_Xh + (size_t)col * IN_F + fl * 8));
    float2 f0 = __half22float2(*reinterpret_cast<__half2*>(&g.x));
    float2 f1 = __half22float2(*reinterpret_cast<__half2*>(&g.y));
    float2 f2 = __half22float2(*reinterpret_cast<__half2*>(&g.z));
    float2 f3 = __half22float2(*reinterpret_cast<__half2*>(&g.w));
    float  v  = __half2float(__ushort_as_half((unsigned short)(p >> 17)));
    a0.x += v * f0.x; a0.y += v * f0.y;
    a0.z += v * f1.x; a0.w += v * f1.y;
    a1.x += v * f2.x; a1.y += v * f2.y;
    a1.z += v * f3.x; a1.w += v * f3.y;
}

__global__ __launch_bounds__(256) void accum_kernel() {
    int t    = blockIdx.x * 256 + threadIdx.x;
    int n    = t >> 5;
    int lane = t & 31;
    if (n >= N_NODES) return;

    const int grp = lane >> 3;         // 0..3: which edge of each 4-edge step
    const int fl  = lane & 7;          // feature octet owned: [fl*8, fl*8+8)

    #pragma unroll
    for (int k = 0; k < SUPPORT; k++) {
        int bin  = k * N_NODES + n;
        int e    = __ldg(&g_start[bin]);
        int eend = __ldg(&g_start[bin + 1]);

        float4 a0 = make_float4(0.f, 0.f, 0.f, 0.f);
        float4 a1 = make_float4(0.f, 0.f, 0.f, 0.f);

        // Full 16-edge blocks: 4 four-edge gathers in flight.
        for (; e + 16 <= eend; e += 16) {
            unsigned int q0 = __ldg(g_pairs + e + 0  + grp);
            unsigned int q1 = __ldg(g_pairs + e + 4  + grp);
            unsigned int q2 = __ldg(g_pairs + e + 8  + grp);
            unsigned int q3 = __ldg(g_pairs + e + 12 + grp);
            gather8(q0, fl, a0, a1);
            gather8(q1, fl, a0, a1);
            gather8(q2, fl, a0, a1);
            gather8(q3, fl, a0, a1);
        }

        // Branchless wide tail: up to 15 remaining edges in one window.
        if (e < eend) {
            int i0 = e + 0  + grp;
            int i1 = e + 4  + grp;
            int i2 = e + 8  + grp;
            int i3 = e + 12 + grp;
            unsigned int q0 = (i0 < eend) ? __ldg(g_pairs + i0) : 0u;
            unsigned int q1 = (i1 < eend) ? __ldg(g_pairs + i1) : 0u;
            unsigned int q2 = (i2 < eend) ? __ldg(g_pairs + i2) : 0u;
            unsigned int q3 = (i3 < eend) ? __ldg(g_pairs + i3) : 0u;
            gather8(q0, fl, a0, a1);
            gather8(q1, fl, a0, a1);
            gather8(q2, fl, a0, a1);
            gather8(q3, fl, a0, a1);
        }

        // Reduce across the 4 lane groups (xor 8, then xor 16).
        #pragma unroll
        for (int off = 8; off <= 16; off <<= 1) {
            a0.x += __shfl_xor_sync(0xffffffffu, a0.x, off);
            a0.y += __shfl_xor_sync(0xffffffffu, a0.y, off);
            a0.z += __shfl_xor_sync(0xffffffffu, a0.z, off);
            a0.w += __shfl_xor_sync(0xffffffffu, a0.w, off);
            a1.x += __shfl_xor_sync(0xffffffffu, a1.x, off);
            a1.y += __shfl_xor_sync(0xffffffffu, a1.y, off);
            a1.z += __shfl_xor_sync(0xffffffffu, a1.z, off);
            a1.w += __shfl_xor_sync(0xffffffffu, a1.w, off);
        }

        if (grp == 0) {
            __half2 h0 = __floats2half2_rn(a0.x, a0.y);
            __half2 h1 = __floats2half2_rn(a0.z, a0.w);
            __half2 h2 = __floats2half2_rn(a1.x, a1.y);
            __half2 h3 = __floats2half2_rn(a1.z, a1.w);
            uint4 pk = make_uint4(*reinterpret_cast<unsigned int*>(&h0),
                                  *reinterpret_cast<unsigned int*>(&h1),
                                  *reinterpret_cast<unsigned int*>(&h2),
                                  *reinterpret_cast<unsigned int*>(&h3));
            *reinterpret_cast<uint4*>(
                g_Yh + ((size_t)k * N_NODES + n) * IN_F + fl * 8) = pk;
        }
    }
}

// ---------------------------------------------------------------------------
// Tensor-core GEMM: out[n][:] = bias + sum_k Yh[k][n][:] @ Wh[k*64:(k+1)*64][:]
// (R10 proven form.)
// ---------------------------------------------------------------------------
__global__ __launch_bounds__(256) void gemm_tc_kernel(const float* __restrict__ bias,
                                                      float* __restrict__ out) {
    __shared__ float Cs[64][72];               // 18.4 KB

    const int tid   = threadIdx.x;
    const int warp  = tid >> 5;
    const int rbase = blockIdx.x * 64;
    const int mt    = warp & 3;                // m-tile (16 rows)
    const int ntb   = (warp >> 2) * 2;         // first of two n-tiles

    wmma::fragment<wmma::accumulator, 16, 16, 16, float> c0, c1;
    wmma::fill_fragment(c0, 0.f);
    wmma::fill_fragment(c1, 0.f);

    #pragma unroll
    for (int ks = 0; ks < SUPPORT; ks++) {
        const __half* Yk  = g_Yh + (size_t)ks * N_NODES * IN_F;
        const __half* Apt = Yk + (size_t)(rbase + mt * 16) * IN_F;
        #pragma unroll
        for (int kc = 0; kc < 4; kc++) {       // 4 x 16 = 64 K per support
            wmma::fragment<wmma::matrix_a, 16, 16, 16, __half, wmma::row_major> a;
            wmma::load_matrix_sync(a, Apt + kc * 16, IN_F);

            const __half* Bpt = g_Wh + (size_t)(ks * 64 + kc * 16) * OUT_F;
            wmma::fragment<wmma::matrix_b, 16, 16, 16, __half, wmma::row_major> b0, b1;
            wmma::load_matrix_sync(b0, Bpt + ntb * 16, OUT_F);
            wmma::load_matrix_sync(b1, Bpt + (ntb + 1) * 16, OUT_F);

            wmma::mma_sync(c0, a, b0, c0);
            wmma::mma_sync(c1, a, b1, c1);
        }
    }

    wmma::store_matrix_sync(&Cs[mt * 16][ntb * 16],       c0, 72, wmma::mem_row_major);
    wmma::store_matrix_sync(&Cs[mt * 16][(ntb + 1) * 16], c1, 72, wmma::mem_row_major);
    __syncthreads();

    #pragma unroll
    for (int i = tid; i < 64 * 16; i += 256) {
        int r  = i >> 4;
        int c4 = i & 15;
        int gr = rbase + r;
        if (gr < N_NODES) {
            float4 b4 = *reinterpret_cast<const float4*>(bias + c4 * 4);
            float4 o  = make_float4(Cs[r][c4 * 4 + 0] + b4.x,
                                    Cs[r][c4 * 4 + 1] + b4.y,
                                    Cs[r][c4 * 4 + 2] + b4.z,
                                    Cs[r][c4 * 4 + 3] + b4.w);
            *reinterpret_cast<float4*>(out + (size_t)gr * OUT_F + c4 * 4) = o;
        }
    }
}

// ---------------------------------------------------------------------------
extern "C" void kernel_launch(void* const* d_in, const int* in_sizes, int n_in,
                              void* d_out, int out_size) {
    const float* X     = (const float*)d_in[0];
    const int*   erows = (const int*)  d_in[1];
    const int*   ecols = (const int*)  d_in[2];
    const float* evals = (const float*)d_in[3];
    const float* W     = (const float*)d_in[4];
    const float* bias  = (const float*)d_in[5];
    float*       out   = (float*)d_out;

    // prep: X->fp16, W->fp16, zero bins (one launch)
    prep_kernel<<<(N_NODES * IN_F / 4 + 255) / 256, 256>>>(X, W);

    // Counting sort of edges by (support, dest row); scatter is atomic-free
    int ebl4 = (TOT_E / 4 + 255) / 256;
    hist_kernel<<<ebl4, 256>>>(erows);
    scanA_kernel<<<NBLK, SCAN_BS>>>();
    scanC_kernel<<<NBLK, SCAN_BS>>>();
    scatter_kernel<<<ebl4, 256>>>(erows, ecols, evals);

    // Y[k][n] = (S_k @ Xh)[n]; warp per node, quarter-warp split + wide tail
    int ablocks = (N_NODES * 32 + 255) / 256;
    accum_kernel<<<ablocks, 256>>>();

    // out = concat_k(Y_k) @ W + bias on tensor cores
    gemm_tc_kernel<<<(N_NODES + 63) / 64, 256>>>(bias, out);
}

// round 16
// speedup vs baseline: 1.0342x; 1.0087x over previous
#include <cuda_runtime.h>
#include <cuda_fp16.h>
#include <mma.h>
#include <cstdint>

using namespace nvcuda;

#define N_NODES 100000
#define N_EDGES 1600000
#define IN_F 64
#define OUT_F 64
#define SUPPORT 3
#define CAT_F (SUPPORT * IN_F)                     // 192

#define M_BINS (SUPPORT * N_NODES)                 // 300000 (k,row) bins
#define TOT_E  (SUPPORT * N_EDGES)                 // 4.8M edges
#define SCAN_BS 1024
#define NBLK ((M_BINS + SCAN_BS - 1) / SCAN_BS)    // 293

// ---- static scratch (no runtime allocation) -------------------------------
__device__ __half             g_Xh[(size_t)N_NODES * IN_F];            // 12.8 MB fp16 X (gather target)
__device__ __half             g_Yh[(size_t)(M_BINS + 64) * IN_F];      // fp16 Y (+pad rows for wmma tail)
__device__ __half             g_Wh[CAT_F * OUT_F];                     // 24 KB fp16 W
__device__ int                g_count[M_BINS];
__device__ int                g_start[M_BINS + 1];
__device__ int                g_partial[SCAN_BS];
__device__ unsigned short     g_rank[TOT_E];       // within-bin rank per edge (9.6 MB)
__device__ unsigned int       g_pairs[TOT_E];      // (val_fp16_15b << 17 | col), bin-sorted (19.2 MB)

// ---------------------------------------------------------------------------
// prep: X->Xh, W->Wh, zero histogram bins (one launch).
// ---------------------------------------------------------------------------
__global__ __launch_bounds__(256) void prep_kernel(const float* __restrict__ X,
                                                   const float* __restrict__ W) {
    int i = blockIdx.x * 256 + threadIdx.x;            // float4 index
    if (i < N_NODES * IN_F / 4) {
        float4 v = reinterpret_cast<const float4*>(X)[i];
        __half2 h0 = __floats2half2_rn(v.x, v.y);
        __half2 h1 = __floats2half2_rn(v.z, v.w);
        uint2 pk = make_uint2(*reinterpret_cast<unsigned int*>(&h0),
                              *reinterpret_cast<unsigned int*>(&h1));
        reinterpret_cast<uint2*>(g_Xh)[i] = pk;
    }
    if (i < CAT_F * OUT_F / 4) {
        float4 v = reinterpret_cast<const float4*>(W)[i];
        __half2 h0 = __floats2half2_rn(v.x, v.y);
        __half2 h1 = __floats2half2_rn(v.z, v.w);
        uint2 pk = make_uint2(*reinterpret_cast<unsigned int*>(&h0),
                              *reinterpret_cast<unsigned int*>(&h1));
        reinterpret_cast<uint2*>(g_Wh)[i] = pk;
    }
    if (i < M_BINS) g_count[i] = 0;
}

// ---------------------------------------------------------------------------
// Counting sort by (support, destination row). hist stores each edge's
// within-bin rank (the atomicAdd return) so scatter needs NO atomics.
// ---------------------------------------------------------------------------
__global__ __launch_bounds__(256) void hist_kernel(const int* __restrict__ rows) {
    int g = blockIdx.x * 256 + threadIdx.x;
    if (g >= TOT_E / 4) return;
    int  e0 = g * 4;
    int  k  = e0 / N_EDGES;
    int4 r4 = *reinterpret_cast<const int4*>(rows + e0);
    int  kb = k * N_NODES;
    int k0 = atomicAdd(&g_count[kb + r4.x], 1);
    int k1 = atomicAdd(&g_count[kb + r4.y], 1);
    int k2 = atomicAdd(&g_count[kb + r4.z], 1);
    int k3 = atomicAdd(&g_count[kb + r4.w], 1);
    ushort4 rk = make_ushort4((unsigned short)k0, (unsigned short)k1,
                              (unsigned short)k2, (unsigned short)k3);
    *reinterpret_cast<ushort4*>(g_rank + e0) = rk;
}

// scanA: block-local exclusive scan via warp-shfl hierarchy (2 barriers).
__global__ __launch_bounds__(SCAN_BS) void scanA_kernel() {
    __shared__ int wsum[32];
    int t    = threadIdx.x;
    int lane = t & 31;
    int wid  = t >> 5;
    int i    = blockIdx.x * SCAN_BS + t;
    int v    = (i < M_BINS) ? g_count[i] : 0;

    // inclusive scan within warp
    int x = v;
    #pragma unroll
    for (int off = 1; off < 32; off <<= 1) {
        int y = __shfl_up_sync(0xffffffffu, x, off);
        if (lane >= off) x += y;
    }
    if (lane == 31) wsum[wid] = x;
    __syncthreads();

    if (wid == 0) {
        int s = wsum[lane];
        #pragma unroll
        for (int off = 1; off < 32; off <<= 1) {
            int y = __shfl_up_sync(0xffffffffu, s, off);
            if (lane >= off) s += y;
        }
        wsum[lane] = s;
    }
    __syncthreads();

    int base = (wid > 0) ? wsum[wid - 1] : 0;
    int incl = base + x;
    if (i < M_BINS) g_start[i] = incl - v;             // exclusive within block
    if (t == SCAN_BS - 1) g_partial[blockIdx.x] = incl;
}

// scanC: block reduces partials[0..bid) via warp-shfl (2 barriers), adds.
__global__ __launch_bounds__(SCAN_BS) void scanC_kernel() {
    __shared__ int wsum[32];
    int t    = threadIdx.x;
    int lane = t & 31;
    int wid  = t >> 5;
    int v    = (t < (int)blockIdx.x && t < NBLK) ? g_partial[t] : 0;

    #pragma unroll
    for (int off = 16; off > 0; off >>= 1)
        v += __shfl_xor_sync(0xffffffffu, v, off);
    if (lane == 0) wsum[wid] = v;
    __syncthreads();

    if (wid == 0) {
        int s = wsum[lane];
        #pragma unroll
        for (int off = 16; off > 0; off >>= 1)
            s += __shfl_xor_sync(0xffffffffu, s, off);
        wsum[lane] = s;                                 // lane0's value = total
    }
    __syncthreads();
    int prefix = wsum[0];

    int i = blockIdx.x * SCAN_BS + t;
    if (i < M_BINS) g_start[i] += prefix;
    if (blockIdx.x == 0 && t == 0) g_start[M_BINS] = TOT_E;
}

// Atomic-free scatter: pos = g_start[bin] + rank[e]. 4B packed payload:
// (fp16 bits of val, sign always 0 -> 15 bits) << 17 | col (<2^17).
__global__ __launch_bounds__(256) void scatter_kernel(const int* __restrict__ rows,
                                                      const int* __restrict__ cols,
                                                      const float* __restrict__ vals) {
    int g = blockIdx.x * 256 + threadIdx.x;
    if (g >= TOT_E / 4) return;
    int    e0 = g * 4;
    int    k  = e0 / N_EDGES;
    int4   r4 = *reinterpret_cast<const int4*>(rows + e0);
    int4   c4 = *reinterpret_cast<const int4*>(cols + e0);
    float4 v4 = *reinterpret_cast<const float4*>(vals + e0);
    ushort4 rk = *reinterpret_cast<const ushort4*>(g_rank + e0);
    int    kb = k * N_NODES;

    int p0 = __ldg(&g_start[kb + r4.x]) + rk.x;
    int p1 = __ldg(&g_start[kb + r4.y]) + rk.y;
    int p2 = __ldg(&g_start[kb + r4.z]) + rk.z;
    int p3 = __ldg(&g_start[kb + r4.w]) + rk.w;

    unsigned int q0 = ((unsigned int)__half_as_ushort(__float2half_rn(v4.x)) << 17) | (unsigned int)c4.x;
    unsigned int q1 = ((unsigned int)__half_as_ushort(__float2half_rn(v4.y)) << 17) | (unsigned int)c4.y;
    unsigned int q2 = ((unsigned int)__half_as_ushort(__float2half_rn(v4.z)) << 17) | (unsigned int)c4.z;
    unsigned int q3 = ((unsigned int)__half_as_ushort(__float2half_rn(v4.w)) << 17) | (unsigned int)c4.w;

    g_pairs[p0] = q0;
    g_pairs[p1] = q1;
    g_pairs[p2] = q2;
    g_pairs[p3] = q3;
}

// ---------------------------------------------------------------------------
// SpMM accumulate: one warp per node, quarter-warp edge split (R13-R15 form).
// p==0 => val bits 0 => 0.0f (harmless row-0 gather).
// ---------------------------------------------------------------------------
__device__ __forceinline__ void gather8(unsigned int p, int fl,
                                        float4& a0, float4& a1) {
    unsigned int col = p & 0x1FFFFu;
    uint4 g = __ldg(reinterpret_cast<const uint4*>(
        g_Xh + (size_t)col * IN_F + fl * 8));
    float2 f0 = __half22float2(*reinterpret_cast<__half2*>(&g.x));
    float2 f1 = __half22float2(*reinterpret_cast<__half2*>(&g.y));
    float2 f2 = __half22float2(*reinterpret_cast<__half2*>(&g.z));
    float2 f3 = __half22float2(*reinterpret_cast<__half2*>(&g.w));
    float  v  = __half2float(__ushort_as_half((unsigned short)(p >> 17)));
    a0.x += v * f0.x; a0.y += v * f0.y;
    a0.z += v * f1.x; a0.w += v * f1.y;
    a1.x += v * f2.x; a1.y += v * f2.y;
    a1.z += v * f3.x; a1.w += v * f3.y;
}

__global__ __launch_bounds__(256) void accum_kernel() {
    int t    = blockIdx.x * 256 + threadIdx.x;
    int n    = t >> 5;
    int lane = t & 31;
    if (n >= N_NODES) return;

    const int grp = lane >> 3;         // 0..3: which edge of each 4-edge step
    const int fl  = lane & 7;          // feature octet owned: [fl*8, fl*8+8)

    #pragma unroll
    for (int k = 0; k < SUPPORT; k++) {
        int bin  = k * N_NODES + n;
        int e    = __ldg(&g_start[bin]);
        int eend = __ldg(&g_start[bin + 1]);

        float4 a0 = make_float4(0.f, 0.f, 0.f, 0.f);
        float4 a1 = make_float4(0.f, 0.f, 0.f, 0.f);

        // Full 16-edge blocks: 4 four-edge gathers in flight.
        for (; e + 16 <= eend; e += 16) {
            unsigned int q0 = __ldg(g_pairs + e + 0  + grp);
            unsigned int q1 = __ldg(g_pairs + e + 4  + grp);
            unsigned int q2 = __ldg(g_pairs + e + 8  + grp);
            unsigned int q3 = __ldg(g_pairs + e + 12 + grp);
            gather8(q0, fl, a0, a1);
            gather8(q1, fl, a0, a1);
            gather8(q2, fl, a0, a1);
            gather8(q3, fl, a0, a1);
        }

        // Branchless wide tail: up to 15 remaining edges in one window.
        if (e < eend) {
            int i0 = e + 0  + grp;
            int i1 = e + 4  + grp;
            int i2 = e + 8  + grp;
            int i3 = e + 12 + grp;
            unsigned int q0 = (i0 < eend) ? __ldg(g_pairs + i0) : 0u;
            unsigned int q1 = (i1 < eend) ? __ldg(g_pairs + i1) : 0u;
            unsigned int q2 = (i2 < eend) ? __ldg(g_pairs + i2) : 0u;
            unsigned int q3 = (i3 < eend) ? __ldg(g_pairs + i3) : 0u;
            gather8(q0, fl, a0, a1);
            gather8(q1, fl, a0, a1);
            gather8(q2, fl, a0, a1);
            gather8(q3, fl, a0, a1);
        }

        // Reduce across the 4 lane groups (xor 8, then xor 16).
        #pragma unroll
        for (int off = 8; off <= 16; off <<= 1) {
            a0.x += __shfl_xor_sync(0xffffffffu, a0.x, off);
            a0.y += __shfl_xor_sync(0xffffffffu, a0.y, off);
            a0.z += __shfl_xor_sync(0xffffffffu, a0.z, off);
            a0.w += __shfl_xor_sync(0xffffffffu, a0.w, off);
            a1.x += __shfl_xor_sync(0xffffffffu, a1.x, off);
            a1.y += __shfl_xor_sync(0xffffffffu, a1.y, off);
            a1.z += __shfl_xor_sync(0xffffffffu, a1.z, off);
            a1.w += __shfl_xor_sync(0xffffffffu, a1.w, off);
        }

        if (grp == 0) {
            __half2 h0 = __floats2half2_rn(a0.x, a0.y);
            __half2 h1 = __floats2half2_rn(a0.z, a0.w);
            __half2 h2 = __floats2half2_rn(a1.x, a1.y);
            __half2 h3 = __floats2half2_rn(a1.z, a1.w);
            uint4 pk = make_uint4(*reinterpret_cast<unsigned int*>(&h0),
                                  *reinterpret_cast<unsigned int*>(&h1),
                                  *reinterpret_cast<unsigned int*>(&h2),
                                  *reinterpret_cast<unsigned int*>(&h3));
            *reinterpret_cast<uint4*>(
                g_Yh + ((size_t)k * N_NODES + n) * IN_F + fl * 8) = pk;
        }
    }
}

// ---------------------------------------------------------------------------
// Tensor-core GEMM: out[n][:] = bias + sum_k Yh[k][n][:] @ Wh[k*64:(k+1)*64][:]
// (R10 proven form.)
// ---------------------------------------------------------------------------
__global__ __launch_bounds__(256) void gemm_tc_kernel(const float* __restrict__ bias,
                                                      float* __restrict__ out) {
    __shared__ float Cs[64][72];               // 18.4 KB

    const int tid   = threadIdx.x;
    const int warp  = tid >> 5;
    const int rbase = blockIdx.x * 64;
    const int mt    = warp & 3;                // m-tile (16 rows)
    const int ntb   = (warp >> 2) * 2;         // first of two n-tiles

    wmma::fragment<wmma::accumulator, 16, 16, 16, float> c0, c1;
    wmma::fill_fragment(c0, 0.f);
    wmma::fill_fragment(c1, 0.f);

    #pragma unroll
    for (int ks = 0; ks < SUPPORT; ks++) {
        const __half* Yk  = g_Yh + (size_t)ks * N_NODES * IN_F;
        const __half* Apt = Yk + (size_t)(rbase + mt * 16) * IN_F;
        #pragma unroll
        for (int kc = 0; kc < 4; kc++) {       // 4 x 16 = 64 K per support
            wmma::fragment<wmma::matrix_a, 16, 16, 16, __half, wmma::row_major> a;
            wmma::load_matrix_sync(a, Apt + kc * 16, IN_F);

            const __half* Bpt = g_Wh + (size_t)(ks * 64 + kc * 16) * OUT_F;
            wmma::fragment<wmma::matrix_b, 16, 16, 16, __half, wmma::row_major> b0, b1;
            wmma::load_matrix_sync(b0, Bpt + ntb * 16, OUT_F);
            wmma::load_matrix_sync(b1, Bpt + (ntb + 1) * 16, OUT_F);

            wmma::mma_sync(c0, a, b0, c0);
            wmma::mma_sync(c1, a, b1, c1);
        }
    }

    wmma::store_matrix_sync(&Cs[mt * 16][ntb * 16],       c0, 72, wmma::mem_row_major);
    wmma::store_matrix_sync(&Cs[mt * 16][(ntb + 1) * 16], c1, 72, wmma::mem_row_major);
    __syncthreads();

    #pragma unroll
    for (int i = tid; i < 64 * 16; i += 256) {
        int r  = i >> 4;
        int c4 = i & 15;
        int gr = rbase + r;
        if (gr < N_NODES) {
            float4 b4 = *reinterpret_cast<const float4*>(bias + c4 * 4);
            float4 o  = make_float4(Cs[r][c4 * 4 + 0] + b4.x,
                                    Cs[r][c4 * 4 + 1] + b4.y,
                                    Cs[r][c4 * 4 + 2] + b4.z,
                                    Cs[r][c4 * 4 + 3] + b4.w);
            *reinterpret_cast<float4*>(out + (size_t)gr * OUT_F + c4 * 4) = o;
        }
    }
}

// ---------------------------------------------------------------------------
extern "C" void kernel_launch(void* const* d_in, const int* in_sizes, int n_in,
                              void* d_out, int out_size) {
    const float* X     = (const float*)d_in[0];
    const int*   erows = (const int*)  d_in[1];
    const int*   ecols = (const int*)  d_in[2];
    const float* evals = (const float*)d_in[3];
    const float* W     = (const float*)d_in[4];
    const float* bias  = (const float*)d_in[5];
    float*       out   = (float*)d_out;

    // prep: X->fp16, W->fp16, zero bins (one launch)
    prep_kernel<<<(N_NODES * IN_F / 4 + 255) / 256, 256>>>(X, W);

    // Counting sort of edges by (support, dest row); scatter is atomic-free
    int ebl4 = (TOT_E / 4 + 255) / 256;
    hist_kernel<<<ebl4, 256>>>(erows);
    scanA_kernel<<<NBLK, SCAN_BS>>>();
    scanC_kernel<<<NBLK, SCAN_BS>>>();
    scatter_kernel<<<ebl4, 256>>>(erows, ecols, evals);

    // Y[k][n] = (S_k @ Xh)[n]; warp per node, quarter-warp split + wide tail
    int ablocks = (N_NODES * 32 + 255) / 256;
    accum_kernel<<<ablocks, 256>>>();

    // out = concat_k(Y_k) @ W + bias on tensor cores
    gemm_tc_kernel<<<(N_NODES + 63) / 64, 256>>>(bias, out);
}